// round 16
// baseline (speedup 1.0000x reference)
#include <cuda_runtime.h>
#include <cuda_fp16.h>
#include <cstdint>
#include <math.h>

#define NN 1024
#define SS 8
#define II 128
#define FF 1024
#define MM 512

// ---------------------------------------------------------------------------
// Scratch (device globals). Pure fp16, single term.
// ---------------------------------------------------------------------------
__device__ __align__(16) __half g_xh[SS * NN * II];
__device__ __align__(16) __half g_wouth[SS * MM * FF];
__device__ __align__(16) __half g_hh[SS * NN * FF];
__device__ int g_xcnt[SS];   // x-slice completion counters (reset by out_mma)

// ---------------------------------------------------------------------------
// Helpers
// ---------------------------------------------------------------------------
__device__ __forceinline__ uint32_t smem_u32(const void* p) {
    uint32_t a;
    asm("{ .reg .u64 t; cvta.to.shared.u64 t, %1; cvt.u32.u64 %0, t; }"
        : "=r"(a) : "l"(p));
    return a;
}

__device__ __forceinline__ void ldsm4(uint32_t* r, uint32_t a) {
    asm volatile("ldmatrix.sync.aligned.m8n8.x4.shared.b16 {%0,%1,%2,%3}, [%4];"
        : "=r"(r[0]), "=r"(r[1]), "=r"(r[2]), "=r"(r[3]) : "r"(a));
}

__device__ __forceinline__ void mma_f16(float* d, const uint32_t* a,
                                        uint32_t b0, uint32_t b1) {
    asm volatile(
        "mma.sync.aligned.m16n8k16.row.col.f32.f16.f16.f32 "
        "{%0,%1,%2,%3}, {%4,%5,%6,%7}, {%8,%9}, {%0,%1,%2,%3};"
        : "+f"(d[0]), "+f"(d[1]), "+f"(d[2]), "+f"(d[3])
        : "r"(a[0]), "r"(a[1]), "r"(a[2]), "r"(a[3]), "r"(b0), "r"(b1));
}

__device__ __forceinline__ void cpasync16(uint32_t dst, const void* src) {
    asm volatile("cp.async.cg.shared.global [%0], [%1], 16;"
        :: "r"(dst), "l"(src));
}
#define CP_COMMIT() asm volatile("cp.async.commit_group;" ::: "memory")
#define CP_WAIT(n)  asm volatile("cp.async.wait_group %0;" :: "n"(n) : "memory")

// fp32 fast nonlinearities (MUFU EX2 + RCP; ~2 ulp)
__device__ __forceinline__ float sigm_fast(float x) {
    return __fdividef(1.f, 1.f + __expf(-x));
}
__device__ __forceinline__ float tanh_fast(float x) {
    return __fdividef(2.f, 1.f + __expf(-2.f * x)) - 1.f;
}

// ---------------------------------------------------------------------------
// PERSISTENT weight-resident gates kernel. 128 CTAs, one per (s, f0).
// Per CTA: (1) convert its 64-row x slice fp32->fp16 into g_xh, publish via
// threadfence+atomic; (2) weight prologue fp32->fp16 into smem (overlaps the
// spin); (3) spin until all 16 x slices of its stream are ready; (4) loop over
// 8 n-tiles with double-buffered cp.async x fill, converting 1/8 of its Wout
// share (1024 float4) each iteration so the Wout DRAM traffic hides under the
// HMMA phase. Warp tile 32(n) x 16(f), 512 threads. Fused LSTM epilogue.
// smem 121856 B.
// ---------------------------------------------------------------------------
__global__ __launch_bounds__(512, 1) void gates_mma(
    const float* __restrict__ mod,
    const float* __restrict__ bi, const float* __restrict__ bg,
    const float* __restrict__ bo,
    const float* __restrict__ Wxi, const float* __restrict__ Wxg,
    const float* __restrict__ Wxo, const float* __restrict__ Wout)
{
    const int bx = blockIdx.x;                    // 0..127
    const int tid = threadIdx.x;

    extern __shared__ __half sm[];
    constexpr int PAD = 136;                      // k-stride (halves), ldsm-clean
    constexpr uint32_t STAGE_E = 128 * PAD;       // x stage, 17408 halves
    constexpr uint32_t OFF_W = 2 * STAGE_E;       // weights: 3 x 64*PAD halves

    const int wid = tid >> 5, lane = tid & 31;
    const int s = bx >> 4, jsl = bx & 15, f0 = jsl * 64;
    const uint32_t sb = smem_u32(sm);

    // ---- convert own x slice: rows [jsl*64, jsl*64+64) of stream s ----
    {
#pragma unroll
        for (int it = 0; it < 4; it++) {
            int idx = tid + it * 512;              // 2048 float4
            int row = jsl * 64 + (idx >> 5), q = idx & 31;
            float4 v = *(const float4*)(mod + (size_t)row * (SS * II)
                                            + s * II + q * 4);
            __half h[4] = {__float2half_rn(v.x), __float2half_rn(v.y),
                           __float2half_rn(v.z), __float2half_rn(v.w)};
            *(uint2*)(g_xh + ((size_t)s * NN + row) * II + q * 4) = *(uint2*)h;
        }
        __threadfence();
        __syncthreads();
        if (tid == 0) atomicAdd(&g_xcnt[s], 1);
    }

    // ---- weight prologue: fp32 LDG -> cvt -> STS (overlaps the spin) ----
    {
        const float* WS[3] = {Wxi, Wxg, Wxo};
#pragma unroll
        for (int g = 0; g < 3; g++) {
            const float* wsrc = WS[g] + ((size_t)s * FF + f0) * II;
#pragma unroll
            for (int it = 0; it < 4; it++) {
                int idx = tid + it * 512;          // 2048 float4 per gate
                int row = idx >> 5, q = idx & 31;
                float4 v = *(const float4*)(wsrc + (size_t)row * II + q * 4);
                __half h[4] = {__float2half_rn(v.x), __float2half_rn(v.y),
                               __float2half_rn(v.z), __float2half_rn(v.w)};
                *(uint2*)(sm + OFF_W + g * 64 * PAD + row * PAD + q * 4) =
                    *(uint2*)h;
            }
        }
    }

    // ---- spin until all 16 slices of stream s are published ----
    if (tid == 0) {
        while (atomicAdd(&g_xcnt[s], 0) < 16) {}
        __threadfence();
    }
    __syncthreads();

    // ---- x-tile fill (cp.async.cg -> L2-coherent): 128 rows x 128 halves ----
    auto fill_x = [&](int n0, uint32_t st) {
        const __half* sa = g_xh + ((size_t)s * NN + n0) * II;
#pragma unroll
        for (int it = 0; it < 4; it++) {
            int idx = tid + it * 512;
            int row = idx >> 4, q = idx & 15;
            cpasync16(sb + 2 * (st + row * PAD + q * 8),
                      sa + (size_t)row * II + q * 8);
        }
    };

    fill_x(0, 0);
    CP_COMMIT();

    const int wm = wid & 3, wn = wid >> 2;
    const int lrA = lane & 15, lcA = (lane >> 4) << 3;
    const int lrB = ((lane >> 4) << 3) + (lane & 7), lcB = ((lane >> 3) & 1) << 3;

    // biases: constant per CTA across the n-loop — load once
    const int fc0 = f0 + wn * 16 + (lane & 3) * 2;
    const int fc1 = fc0 + 8;
    const float bia[4] = {bi[(size_t)s * FF + fc0], bi[(size_t)s * FF + fc0 + 1],
                          bi[(size_t)s * FF + fc1], bi[(size_t)s * FF + fc1 + 1]};
    const float bga[4] = {bg[(size_t)s * FF + fc0], bg[(size_t)s * FF + fc0 + 1],
                          bg[(size_t)s * FF + fc1], bg[(size_t)s * FF + fc1 + 1]};
    const float boa[4] = {bo[(size_t)s * FF + fc0], bo[(size_t)s * FF + fc0 + 1],
                          bo[(size_t)s * FF + fc1], bo[(size_t)s * FF + fc1 + 1]};

    int stage = 0;
#pragma unroll 1
    for (int i = 0; i < 8; i++) {
        const int n0 = i * 128;
        if (i + 1 < 8) fill_x(n0 + 128, (uint32_t)(stage ^ 1) * STAGE_E);
        CP_COMMIT();

        // ---- overlapped Wout convert: this CTA's share, 1024 float4/iter ----
        // LDGs issued here ride under the cp.async wait + HMMA phase below.
        {
            const float4* src = (const float4*)Wout;
            size_t base4 = (size_t)bx * 8192 + (size_t)i * 1024;
#pragma unroll
            for (int it = 0; it < 2; it++) {
                size_t j = base4 + it * 512 + tid;
                float4 v = src[j];
                __half h[4] = {__float2half_rn(v.x), __float2half_rn(v.y),
                               __float2half_rn(v.z), __float2half_rn(v.w)};
                *(uint2*)(g_wouth + j * 4) = *(uint2*)h;
            }
        }

        CP_WAIT(1);                 // current x stage complete
        __syncthreads();            // also orders the weight STS (first iter)

        const uint32_t st = (uint32_t)stage * STAGE_E;

        float acc[3][2][2][4];
#pragma unroll
        for (int g = 0; g < 3; g++)
#pragma unroll
            for (int mb = 0; mb < 2; mb++)
#pragma unroll
                for (int nb = 0; nb < 2; nb++)
#pragma unroll
                    for (int e = 0; e < 4; e++) acc[g][mb][nb][e] = 0.f;

        const uint32_t aAh = sb + 2 * (st + (wm * 32 + lrA) * PAD + lcA);

#pragma unroll
        for (int kk = 0; kk < 8; kk++) {
            const int k0 = kk * 16;
            uint32_t ah[2][4];
            ldsm4(ah[0], aAh + 2 * k0);
            ldsm4(ah[1], aAh + 2 * (16 * PAD + k0));
#pragma unroll
            for (int g = 0; g < 3; g++) {
                const uint32_t bgb = sb + 2 * (OFF_W + g * 64 * PAD
                                     + (wn * 16 + lrB) * PAD + k0 + lcB);
                uint32_t bh[4];
                ldsm4(bh, bgb);
#pragma unroll
                for (int mb = 0; mb < 2; mb++)
#pragma unroll
                    for (int nb = 0; nb < 2; nb++)
                        mma_f16(acc[g][mb][nb], ah[mb], bh[nb * 2], bh[nb * 2 + 1]);
            }
        }

        // ---- fused LSTM epilogue: h = sigm(o)*tanh(sigm(i)*tanh(g)) ----
#pragma unroll
        for (int nb = 0; nb < 2; nb++) {
            const int fc = (nb == 0) ? fc0 : fc1;
#pragma unroll
            for (int mb = 0; mb < 2; mb++)
#pragma unroll
                for (int hf = 0; hf < 2; hf++) {
                    const int n = n0 + wm * 32 + mb * 16 + (lane >> 2) + hf * 8;
                    const size_t off = ((size_t)s * NN + n) * FF + fc;
                    float h2[2];
#pragma unroll
                    for (int e = 0; e < 2; e++) {
                        float pi = acc[0][mb][nb][hf * 2 + e] + bia[nb * 2 + e];
                        float pg = acc[1][mb][nb][hf * 2 + e] + bga[nb * 2 + e];
                        float po = acc[2][mb][nb][hf * 2 + e] + boa[nb * 2 + e];
                        float cv = sigm_fast(pi) * tanh_fast(pg);
                        h2[e] = sigm_fast(po) * tanh_fast(cv);
                    }
                    *(__half2*)(g_hh + off) = __floats2half2_rn(h2[0], h2[1]);
                }
        }
        __syncthreads();            // all reads of this x stage done
        stage ^= 1;
    }
}

// ---------------------------------------------------------------------------
// Out kernel: CTA tile 128(n) x 128(m). 256 threads = 8 warps (2x4),
// warp tile 64(n) x 32(m). K=1024 in 16 chunks of 64, 3-stage cp.async
// pipeline with ONE sync per iteration. 2 CTAs/SM (smem 110592 B).
// Also resets g_xcnt for the next graph replay (block (0,0,0)).
// ---------------------------------------------------------------------------
__global__ __launch_bounds__(256, 2) void out_mma(
    const float* __restrict__ bout, float* __restrict__ out)
{
    extern __shared__ __half sm[];
    constexpr int PB = 72;                         // 64-chunk row stride, clean
    constexpr uint32_t TEN = 128 * PB;             // 9216 halves per tensor
    constexpr uint32_t STG_B = 2u * TEN * 2;       // 36864 B per stage, 3 stages

    const int tid = threadIdx.x, wid = tid >> 5, lane = tid & 31;
    const int s = blockIdx.z, n0 = blockIdx.x * 128, m0 = blockIdx.y * 128;
    const uint32_t sb = smem_u32(sm);

    // reset x-slice counters for next replay
    if (blockIdx.x == 0 && blockIdx.y == 0 && blockIdx.z == 0 && tid < SS)
        g_xcnt[tid] = 0;

    const __half* gA = g_hh    + ((size_t)s * NN + n0) * FF;
    const __half* gB = g_wouth + ((size_t)s * MM + m0) * FF;

    auto load = [&](int ch, int stg) {
        const int kc = ch * 64;
        const uint32_t base = sb + (uint32_t)stg * STG_B;
#pragma unroll
        for (int it = 0; it < 4; it++) {
            int idx = tid + it * 256;              // 1024 positions
            int row = idx >> 3, q = idx & 7;       // 128 rows x 8 x 16B
            const uint32_t d = 2 * (row * PB + q * 8);
            const size_t so = (size_t)row * FF + kc + q * 8;
            cpasync16(base + d,           gA + so);
            cpasync16(base + 2 * TEN + d, gB + so);
        }
    };

    const int wm = wid & 1, wn = wid >> 1;
    const int lrA = lane & 15, lcA = (lane >> 4) << 3;
    const int lrB = ((lane >> 4) << 3) + (lane & 7), lcB = ((lane >> 3) & 1) << 3;

    float acc[4][4][4];
#pragma unroll
    for (int mb = 0; mb < 4; mb++)
#pragma unroll
        for (int nb = 0; nb < 4; nb++)
#pragma unroll
            for (int e = 0; e < 4; e++) acc[mb][nb][e] = 0.f;

    load(0, 0); CP_COMMIT();
    load(1, 1); CP_COMMIT();

#pragma unroll 1
    for (int ch = 0; ch < 16; ch++) {
        CP_WAIT(1);
        __syncthreads();
        // stage (ch+2)%3 == stage (ch-1)%3 was fully read at iter ch-1
        if (ch + 2 < 16) load(ch + 2, (ch + 2) % 3);
        CP_COMMIT();

        const int stg = ch % 3;
        const uint32_t base = sb + (uint32_t)stg * STG_B;
        const uint32_t aA = base + 2 * ((wm * 64 + lrA) * PB + lcA);
        const uint32_t aB = base + 2 * (TEN + (wn * 32 + lrB) * PB + lcB);

#pragma unroll
        for (int kk = 0; kk < 4; kk++) {
            const int k0 = kk * 16;
            uint32_t ah[4][4], bh[2][4];
#pragma unroll
            for (int mb = 0; mb < 4; mb++)
                ldsm4(ah[mb], aA + 2 * (mb * 16 * PB + k0));
#pragma unroll
            for (int p = 0; p < 2; p++)
                ldsm4(bh[p], aB + 2 * (p * 16 * PB + k0));
#pragma unroll
            for (int mb = 0; mb < 4; mb++)
#pragma unroll
                for (int nb = 0; nb < 4; nb++)
                    mma_f16(acc[mb][nb], ah[mb],
                            bh[nb >> 1][(nb & 1) * 2], bh[nb >> 1][(nb & 1) * 2 + 1]);
        }
    }

    // ---- epilogue: bias + fp32 store ----
#pragma unroll
    for (int nb = 0; nb < 4; nb++) {
        const int mc = m0 + wn * 32 + nb * 8 + (lane & 3) * 2;
        const float b0 = bout[(size_t)s * MM + mc];
        const float b1 = bout[(size_t)s * MM + mc + 1];
#pragma unroll
        for (int mb = 0; mb < 4; mb++)
#pragma unroll
            for (int hf = 0; hf < 2; hf++) {
                const int n = n0 + wm * 64 + mb * 16 + (lane >> 2) + hf * 8;
                float2 v = make_float2(acc[mb][nb][hf * 2] + b0,
                                       acc[mb][nb][hf * 2 + 1] + b1);
                *(float2*)(out + (size_t)n * (SS * MM) + s * MM + mc) = v;
            }
    }
}

// ---------------------------------------------------------------------------
// Launch. Inputs: modulation, Wxi, Whi, bi, Wxf, Whf, bf, Wxg, Whg, bg,
// Wxo, Who, bo, Wout, bout. h0 = c0 = 0 kills Whi/Wxf/Whf/bf/Whg/Who.
// ---------------------------------------------------------------------------
extern "C" void kernel_launch(void* const* d_in, const int* in_sizes, int n_in,
                              void* d_out, int out_size) {
    const float* mod  = (const float*)d_in[0];
    const float* Wxi  = (const float*)d_in[1];
    const float* bi   = (const float*)d_in[3];
    const float* Wxg  = (const float*)d_in[7];
    const float* bg   = (const float*)d_in[9];
    const float* Wxo  = (const float*)d_in[10];
    const float* bo   = (const float*)d_in[12];
    const float* Wout = (const float*)d_in[13];
    const float* bout = (const float*)d_in[14];
    float* out = (float*)d_out;

    cudaFuncSetAttribute(gates_mma, cudaFuncAttributeMaxDynamicSharedMemorySize, 121856);
    cudaFuncSetAttribute(out_mma,   cudaFuncAttributeMaxDynamicSharedMemorySize, 110592);

    // 128 persistent gates CTAs; x convert + Wout convert fully in-kernel
    gates_mma<<<128, 512, 121856>>>(mod, bi, bg, bo, Wxi, Wxg, Wxo, Wout);

    dim3 gOut(NN / 128, MM / 128, SS);             // (8, 4, 8)
    out_mma<<<gOut, 256, 110592>>>(bout, out);
}